// round 9
// baseline (speedup 1.0000x reference)
#include <cuda_runtime.h>
#include <cuda_bf16.h>
#include <math.h>
#include <stdint.h>

// ---------------- problem constants ----------------
#define BB   256
#define TT   512
#define HH   1024
#define NCTA 128
#define NTHR 512      // 16 warps: 2 (M half) x 8 (N octet)

// 128 CTAs = 32 mi (32 neurons each) x 4 nb (64 batches each); full K per CTA.
// SMEM: A frags (W hi 64K + lo 64K) resident | 2 chunk bufs (hi16K+lo16K each)
#define OFF_AHI 0
#define OFF_ALO 65536
#define OFF_CH  131072
#define SMEM_SZ 196608

// ---------------- device globals ----------------
// h in B-fragment order, ping-pong: [buf][nb][kk 64][o 8][lane 32][slot 2] u32
// u32 = (bf16 even-n, bf16 odd-n). hi and lo split planes.
__device__ __align__(16) uint32_t g_hhi[2][4][32768];    // 2 x 512 KB
__device__ __align__(16) uint32_t g_hlo[2][4][32768];
__device__ volatile int g_done[NCTA];                    // per-step publish flags
__device__ volatile int g_flags[NCTA];                   // one-time init barrier

__device__ __forceinline__ uint32_t pack_bf(float x, float y) {
    __nv_bfloat162 v = __floats2bfloat162_rn(x, y);      // low = x, high = y
    return *reinterpret_cast<uint32_t*>(&v);
}
__device__ __forceinline__ void mma16816(float* c, const uint32_t* a,
                                         const uint32_t* b) {
    asm volatile(
        "mma.sync.aligned.m16n8k16.row.col.f32.bf16.bf16.f32 "
        "{%0,%1,%2,%3}, {%4,%5,%6,%7}, {%8,%9}, {%0,%1,%2,%3};"
        : "+f"(c[0]), "+f"(c[1]), "+f"(c[2]), "+f"(c[3])
        : "r"(a[0]), "r"(a[1]), "r"(a[2]), "r"(a[3]), "r"(b[0]), "r"(b[1]));
}
__device__ __forceinline__ float ftanh(float x) {
    float e = __expf(2.f * x);
    return 1.f - __fdividef(2.f, e + 1.f);
}

extern "C" __global__ void __launch_bounds__(NTHR, 1)
rnn_decoder_kernel(const float* __restrict__ init_in,   // [B,1]
                   const float* __restrict__ hidden0,   // [B,H]
                   const float* __restrict__ targets,   // [T,B,1]
                   const float* __restrict__ W_ih,      // [H,1]
                   const float* __restrict__ W_hh,      // [H,H]
                   const float* __restrict__ b_ih,      // [H]
                   const float* __restrict__ b_hh,      // [H]
                   const float* __restrict__ W_out,     // [1,H]
                   const float* __restrict__ b_out,     // [1]
                   float* __restrict__ out)             // [T,B,1]
{
    extern __shared__ __align__(16) char smem[];
    uint32_t sb;
    asm("{ .reg .u64 t; cvta.to.shared.u64 t, %1; cvt.u32.u64 %0, t; }"
        : "=r"(sb) : "l"(smem));

    const int tid  = threadIdx.x;
    const int cta  = blockIdx.x;
    const int wid  = tid >> 5;
    const int lane = tid & 31;
    const int g    = lane >> 2;
    const int tq   = lane & 3;
    const int wmh  = wid & 1;            // M half (16 rows)
    const int wng  = wid >> 1;           // N octet (8 batch cols)

    const int mi  = cta >> 2;            // 0..31
    const int nb  = cta & 3;             // 0..3
    const int m0  = mi * 32;
    const int bb0 = nb * 64;

    const int base_g = g_flags[cta];
    const int base_d = g_done[cta];

    // ---- one-time: A fragments (W hi+lo) in exact mma lane order ----
    {
        const int r0 = m0 + wmh * 16 + g;
        const int r1 = r0 + 8;
        for (int jj = 0; jj < 8; jj++) {
            const int kk = (wid >> 1) + 8 * jj;          // 0..63
            const int c  = kk * 16 + 2 * tq;
            float w00 = W_hh[(size_t)r0 * HH + c];
            float w01 = W_hh[(size_t)r0 * HH + c + 1];
            float w04 = W_hh[(size_t)r0 * HH + c + 8];
            float w05 = W_hh[(size_t)r0 * HH + c + 9];
            float w10 = W_hh[(size_t)r1 * HH + c];
            float w11 = W_hh[(size_t)r1 * HH + c + 1];
            float w14 = W_hh[(size_t)r1 * HH + c + 8];
            float w15 = W_hh[(size_t)r1 * HH + c + 9];
            uint4 hi, lo;
            hi.x = pack_bf(w00, w01);
            hi.y = pack_bf(w10, w11);
            hi.z = pack_bf(w04, w05);
            hi.w = pack_bf(w14, w15);
            lo.x = pack_bf(w00 - __bfloat162float(__float2bfloat16(w00)),
                           w01 - __bfloat162float(__float2bfloat16(w01)));
            lo.y = pack_bf(w10 - __bfloat162float(__float2bfloat16(w10)),
                           w11 - __bfloat162float(__float2bfloat16(w11)));
            lo.z = pack_bf(w04 - __bfloat162float(__float2bfloat16(w04)),
                           w05 - __bfloat162float(__float2bfloat16(w05)));
            lo.w = pack_bf(w14 - __bfloat162float(__float2bfloat16(w14)),
                           w15 - __bfloat162float(__float2bfloat16(w15)));
            const int ob = (wmh * 64 + kk) * 512 + lane * 16;
            *reinterpret_cast<uint4*>(smem + OFF_AHI + ob) = hi;
            *reinterpret_cast<uint4*>(smem + OFF_ALO + ob) = lo;
        }
    }

    // ---- one-time: publish hidden0 slice (my 32 n x 64 b) into buf 1 ----
    {
        const int b  = tid >> 3;                         // 0..63
        const int pp = tid & 7;
#pragma unroll
        for (int pi = 0; pi < 2; pi++) {
            const int nl = 2 * (pp + 8 * pi);            // local n pair 0..30
            const int n  = m0 + nl;
            float v0 = hidden0[(size_t)(bb0 + b) * HH + n];
            float v1 = hidden0[(size_t)(bb0 + b) * HH + n + 1];
            __nv_bfloat16 h0 = __float2bfloat16(v0);
            __nv_bfloat16 h1 = __float2bfloat16(v1);
            uint32_t uhi = (uint32_t)__bfloat16_as_ushort(h0) |
                           ((uint32_t)__bfloat16_as_ushort(h1) << 16);
            uint32_t ulo = pack_bf(v0 - __bfloat162float(h0),
                                   v1 - __bfloat162float(h1));
            const int kkL = nl >> 4, slot = (nl >> 3) & 1, tqt = (nl & 7) >> 1;
            const int o = b >> 3, lt = (b & 7) * 4 + tqt;
            const int idx = ((kkL * 8 + o) * 32 + lt) * 2 + slot;
            g_hhi[1][nb][mi * 1024 + idx] = uhi;
            g_hlo[1][nb][mi * 1024 + idx] = ulo;
        }
    }
    // ---- one-time: out init to b_out ----
    {
        const float bo = b_out[0];
        out[(size_t)cta * 1024 + tid]       = bo;
        out[(size_t)cta * 1024 + 512 + tid] = bo;
    }
    // epilogue constants for my rows
    const int rl0 = wmh * 16 + g;
    const int r0g = m0 + rl0, r1g = r0g + 8;
    const float bias0 = b_ih[r0g] + b_hh[r0g], bias1 = b_ih[r1g] + b_hh[r1g];
    const float wih0 = W_ih[r0g], wih1 = W_ih[r1g];
    const float wout0 = W_out[r0g], wout1 = W_out[r1g];
    const int bl0 = wng * 8 + 2 * tq;

    // ---- one-time grid barrier ----
    __threadfence();
    __syncthreads();
    if (tid == 0) g_flags[cta] = base_g + 1;
    if (tid < 32) {
        const int tgt = base_g + 1;
        bool ok;
        do {
            int a = g_flags[tid];
            int b = g_flags[tid + 32];
            int c = g_flags[tid + 64];
            int d = g_flags[tid + 96];
            ok = (a >= tgt) & (b >= tgt) & (c >= tgt) & (d >= tgt);
        } while (!__all_sync(0xffffffffu, ok));
        __threadfence();
    }
    __syncthreads();

#pragma unroll 1
    for (int t = 0; t < TT; t++) {
        const int rbuf = (t + 1) & 1, wbuf = t & 1;
        const char* srcH = (const char*)&g_hhi[rbuf][nb][0];
        const char* srcL = (const char*)&g_hlo[rbuf][nb][0];
        const int tgt = base_d + t;                      // h(t-1) flags
        unsigned ready = 0;                              // warp0 ballot cache

        // prefetch x for my batch cols
        const float* xsrc = (t == 0) ? init_in : (targets + (size_t)(t - 1) * BB);
        const float xv0 = xsrc[bb0 + bl0];
        const float xv1 = xsrc[bb0 + bl0 + 1];

        auto poll = [&](int j) {
            if (wid == 0) {
                const unsigned need = 0xFu << (4 * j);
                while ((ready & need) != need) {
                    bool ok = (g_done[lane * 4 + nb] >= tgt);
                    ready = __ballot_sync(0xffffffffu, ok);
                }
                __threadfence();
            }
        };
        auto cpchunk = [&](int j, int p) {
            const uint32_t dh = sb + OFF_CH + p * 32768;
#pragma unroll
            for (int k2 = 0; k2 < 2; k2++) {
                const int e = (tid + k2 * 512) * 16;
                asm volatile("cp.async.cg.shared.global [%0], [%1], 16;"
                             :: "r"(dh + e), "l"(srcH + j * 16384 + e));
                asm volatile("cp.async.cg.shared.global [%0], [%1], 16;"
                             :: "r"(dh + 16384 + e), "l"(srcL + j * 16384 + e));
            }
            asm volatile("cp.async.commit_group;" ::: "memory");
        };

        poll(0);
        __syncthreads();
        cpchunk(0, 0);

        float acc[4] = {0.f, 0.f, 0.f, 0.f};

#pragma unroll 1
        for (int j = 0; j < 8; j++) {
            if (j < 7) {
                poll(j + 1);
                __syncthreads();
                cpchunk(j + 1, (j + 1) & 1);
                asm volatile("cp.async.wait_group 1;" ::: "memory");
            } else {
                asm volatile("cp.async.wait_group 0;" ::: "memory");
            }
            __syncthreads();

            const int abase = (wmh * 64 + j * 8) * 512 + lane * 16;
            const int bbase = OFF_CH + (j & 1) * 32768 + wng * 256 + lane * 8;
#pragma unroll
            for (int k8 = 0; k8 < 8; k8++) {
                uint4 Ah = *reinterpret_cast<const uint4*>(smem + abase + k8 * 512);
                uint4 Al = *reinterpret_cast<const uint4*>(smem + OFF_ALO + abase + k8 * 512);
                uint2 Bh = *reinterpret_cast<const uint2*>(smem + bbase + k8 * 2048);
                uint2 Bl = *reinterpret_cast<const uint2*>(smem + bbase + k8 * 2048 + 16384);
                mma16816(acc, &Ah.x, &Bh.x);
                mma16816(acc, &Al.x, &Bh.x);
                mma16816(acc, &Ah.x, &Bl.x);
            }
        }

        // ---- epilogue: bias + x term, tanh, y, publish h frags ----
        float h0 = ftanh(acc[0] + fmaf(xv0, wih0, bias0));
        float h1 = ftanh(acc[1] + fmaf(xv1, wih0, bias0));
        float h2 = ftanh(acc[2] + fmaf(xv0, wih1, bias1));
        float h3 = ftanh(acc[3] + fmaf(xv1, wih1, bias1));

        float yb0 = h0 * wout0 + h2 * wout1;
        float yb1 = h1 * wout0 + h3 * wout1;
#pragma unroll
        for (int o = 4; o < 32; o <<= 1) {
            yb0 += __shfl_xor_sync(0xffffffffu, yb0, o);
            yb1 += __shfl_xor_sync(0xffffffffu, yb1, o);
        }
        if (lane < 4) {
            atomicAdd(&out[(size_t)t * BB + bb0 + wng * 8 + 2 * lane],     yb0);
            atomicAdd(&out[(size_t)t * BB + bb0 + wng * 8 + 2 * lane + 1], yb1);
        }

        // scatter h into frag-ordered staging (buf0 region; mma(7) used buf1)
        unsigned short* sth = reinterpret_cast<unsigned short*>(smem + OFF_CH);
        unsigned short* stl = reinterpret_cast<unsigned short*>(smem + OFF_CH + 4096);
        {
            const float hv[4] = {h0, h1, h2, h3};
#pragma unroll
            for (int q = 0; q < 4; q++) {
                const int rl = rl0 + (q >> 1) * 8;
                const int bl = bl0 + (q & 1);
                const int kkL = rl >> 4, slot = (rl >> 3) & 1;
                const int tqt = (rl & 7) >> 1, par = rl & 1;
                const int o = bl >> 3, lt = (bl & 7) * 4 + tqt;
                const int idx = ((kkL * 8 + o) * 32 + lt) * 2 + slot;
                __nv_bfloat16 hb = __float2bfloat16(hv[q]);
                sth[idx * 2 + par] = __bfloat16_as_ushort(hb);
                stl[idx * 2 + par] = __bfloat16_as_ushort(
                    __float2bfloat16(hv[q] - __bfloat162float(hb)));
            }
        }
        __syncthreads();
        {
            uint2 vh = reinterpret_cast<const uint2*>(smem + OFF_CH)[tid];
            uint2 vl = reinterpret_cast<const uint2*>(smem + OFF_CH + 4096)[tid];
            reinterpret_cast<uint2*>(&g_hhi[wbuf][nb][mi * 1024])[tid] = vh;
            reinterpret_cast<uint2*>(&g_hlo[wbuf][nb][mi * 1024])[tid] = vl;
        }
        __threadfence();
        __syncthreads();
        if (tid == 0) g_done[cta] = base_d + t + 1;
    }
}

extern "C" void kernel_launch(void* const* d_in, const int* in_sizes, int n_in,
                              void* d_out, int out_size) {
    const float* init_in = (const float*)d_in[0];
    const float* hidden0 = (const float*)d_in[1];
    const float* targets = (const float*)d_in[2];
    const float* W_ih    = (const float*)d_in[3];
    const float* W_hh    = (const float*)d_in[4];
    const float* b_ih    = (const float*)d_in[5];
    const float* b_hh    = (const float*)d_in[6];
    const float* W_out   = (const float*)d_in[7];
    const float* b_out   = (const float*)d_in[8];
    float* out = (float*)d_out;

    cudaFuncSetAttribute(rnn_decoder_kernel,
                         cudaFuncAttributeMaxDynamicSharedMemorySize, SMEM_SZ);
    rnn_decoder_kernel<<<NCTA, NTHR, SMEM_SZ>>>(init_in, hidden0, targets, W_ih,
                                                W_hh, b_ih, b_hh, W_out, b_out,
                                                out);
}

// round 10
// speedup vs baseline: 1.1447x; 1.1447x over previous
#include <cuda_runtime.h>
#include <cuda_bf16.h>
#include <math.h>
#include <stdint.h>

// ---------------- problem constants ----------------
#define BB   256
#define TT   512
#define HH   1024
#define NCTA 128
#define NTHR 256      // 8 warps = 4 pairs; pair = {wmh0, wmh1} x 16 batch cols

// 128 CTAs = 32 mi (32 neurons) x 4 nb (64 batch); full K per CTA.
// SMEM: A frags (W hi 64K | lo 64K) resident | per-pair B chunk bufs 4 x 16K
#define OFF_ALO 65536
#define OFF_B   131072
#define SMEM_SZ 196608

// ---------------- device globals ----------------
// h in fused B-frag order: [buf][nb][kk 64][oct 8][lane 32] uint4 =
//   (hi slot0, hi slot1, lo slot0, lo slot1); each u32 = bf16 pair (par0,par1)
__device__ __align__(16) uint4 g_hb[2][4][64][8][32];    // 4 MB
__device__ volatile int g_dw[NCTA * 4];                  // per (cta, pair) flags
__device__ volatile int g_flags[NCTA];                   // one-time init barrier

__device__ __forceinline__ uint32_t pack_bf(float x, float y) {
    __nv_bfloat162 v = __floats2bfloat162_rn(x, y);
    return *reinterpret_cast<uint32_t*>(&v);
}
__device__ __forceinline__ unsigned short bhi(float x) {
    return __bfloat16_as_ushort(__float2bfloat16(x));
}
__device__ __forceinline__ float bup(unsigned short u) {
    return __bfloat162float(__ushort_as_bfloat16(u));
}
__device__ __forceinline__ void mma16816(float* c, const uint32_t* a,
                                         const uint32_t* b) {
    asm volatile(
        "mma.sync.aligned.m16n8k16.row.col.f32.bf16.bf16.f32 "
        "{%0,%1,%2,%3}, {%4,%5,%6,%7}, {%8,%9}, {%0,%1,%2,%3};"
        : "+f"(c[0]), "+f"(c[1]), "+f"(c[2]), "+f"(c[3])
        : "r"(a[0]), "r"(a[1]), "r"(a[2]), "r"(a[3]), "r"(b[0]), "r"(b[1]));
}
__device__ __forceinline__ float ftanh(float x) {
    float e = __expf(2.f * x);
    return 1.f - __fdividef(2.f, e + 1.f);
}

extern "C" __global__ void __launch_bounds__(NTHR, 1)
rnn_decoder_kernel(const float* __restrict__ init_in,   // [B,1]
                   const float* __restrict__ hidden0,   // [B,H]
                   const float* __restrict__ targets,   // [T,B,1]
                   const float* __restrict__ W_ih,      // [H,1]
                   const float* __restrict__ W_hh,      // [H,H]
                   const float* __restrict__ b_ih,      // [H]
                   const float* __restrict__ b_hh,      // [H]
                   const float* __restrict__ W_out,     // [1,H]
                   const float* __restrict__ b_out,     // [1]
                   float* __restrict__ out)             // [T,B,1]
{
    extern __shared__ __align__(16) char smem[];
    uint32_t sb;
    asm("{ .reg .u64 t; cvta.to.shared.u64 t, %1; cvt.u32.u64 %0, t; }"
        : "=r"(sb) : "l"(smem));

    const int tid  = threadIdx.x;
    const int cta  = blockIdx.x;
    const int wid  = tid >> 5;
    const int lane = tid & 31;
    const int g    = lane >> 2;
    const int tq   = lane & 3;
    const int wmh  = wid & 1;            // M half (16 rows) within pair
    const int w    = wid >> 1;           // pair id 0..3 (16 batch cols each)

    const int mi  = cta >> 2;            // 0..31
    const int nb  = cta & 3;             // 0..3
    const int m0  = mi * 32;
    const int bb0 = nb * 64;

    const int base_g = g_flags[cta];
    const int base_d = g_dw[cta * 4 + w];

    // ---- one-time: A fragments (W hi+lo) in exact mma lane order ----
    {
        const int r0 = m0 + wmh * 16 + g;
        const int r1 = r0 + 8;
        const int ks = wid >> 1;                         // kk slot 0..3
        for (int jj = 0; jj < 16; jj++) {
            const int kk = ks + 4 * jj;                  // 0..63
            const int c  = kk * 16 + 2 * tq;
            float w00 = W_hh[(size_t)r0 * HH + c];
            float w01 = W_hh[(size_t)r0 * HH + c + 1];
            float w04 = W_hh[(size_t)r0 * HH + c + 8];
            float w05 = W_hh[(size_t)r0 * HH + c + 9];
            float w10 = W_hh[(size_t)r1 * HH + c];
            float w11 = W_hh[(size_t)r1 * HH + c + 1];
            float w14 = W_hh[(size_t)r1 * HH + c + 8];
            float w15 = W_hh[(size_t)r1 * HH + c + 9];
            uint4 hi, lo;
            hi.x = pack_bf(w00, w01);
            hi.y = pack_bf(w10, w11);
            hi.z = pack_bf(w04, w05);
            hi.w = pack_bf(w14, w15);
            lo.x = pack_bf(w00 - bup(bhi(w00)), w01 - bup(bhi(w01)));
            lo.y = pack_bf(w10 - bup(bhi(w10)), w11 - bup(bhi(w11)));
            lo.z = pack_bf(w04 - bup(bhi(w04)), w05 - bup(bhi(w05)));
            lo.w = pack_bf(w14 - bup(bhi(w14)), w15 - bup(bhi(w15)));
            const int ob = (wmh * 64 + kk) * 512 + lane * 16;
            *reinterpret_cast<uint4*>(smem + ob)           = hi;
            *reinterpret_cast<uint4*>(smem + OFF_ALO + ob) = lo;
        }
    }

    // ---- one-time: publish h0 slice (fused uint4 frags), even-g lanes ----
    if ((g & 1) == 0) {
#pragma unroll
        for (int o = 0; o < 2; o++)
#pragma unroll
            for (int c = 0; c < 2; c++) {
                const int col = bb0 + w * 16 + o * 8 + 2 * tq + c;
                const int rA = m0 + wmh * 16 + g;
                float va = hidden0[(size_t)col * HH + rA];
                float vb = hidden0[(size_t)col * HH + rA + 1];
                float vc = hidden0[(size_t)col * HH + rA + 8];
                float vd = hidden0[(size_t)col * HH + rA + 9];
                uint4 u;
                u.x = (uint32_t)bhi(va) | ((uint32_t)bhi(vb) << 16);
                u.y = (uint32_t)bhi(vc) | ((uint32_t)bhi(vd) << 16);
                u.z = pack_bf(va - bup(bhi(va)), vb - bup(bhi(vb)));
                u.w = pack_bf(vc - bup(bhi(vc)), vd - bup(bhi(vd)));
                g_hb[1][nb][mi * 2 + wmh][2 * w + o][(2 * tq + c) * 4 + (g >> 1)] = u;
            }
    }
    // ---- one-time: out init to b_out ----
    {
        const float bo = b_out[0];
#pragma unroll
        for (int k = 0; k < 4; k++) out[(size_t)cta * 1024 + k * 256 + tid] = bo;
    }

    // epilogue constants for my 2 rows / 4 cols
    const int r0g = m0 + wmh * 16 + g, r8g = r0g + 8;
    const float bias_g = b_ih[r0g] + b_hh[r0g], bias_8 = b_ih[r8g] + b_hh[r8g];
    const float wih_g = W_ih[r0g], wih_8 = W_ih[r8g];
    const float wout_g = W_out[r0g], wout_8 = W_out[r8g];

    // ---- one-time grid barrier ----
    __threadfence();
    __syncthreads();
    if (tid == 0) g_flags[cta] = base_g + 1;
    if (tid < 32) {
        const int tgt = base_g + 1;
        bool ok;
        do {
            int a = g_flags[tid];
            int b = g_flags[tid + 32];
            int c = g_flags[tid + 64];
            int d = g_flags[tid + 96];
            ok = (a >= tgt) & (b >= tgt) & (c >= tgt) & (d >= tgt);
        } while (!__all_sync(0xffffffffu, ok));
        __threadfence();
    }
    __syncthreads();

    const int barid = 1 + w;             // named barrier per pair (64 threads)

#pragma unroll 1
    for (int t = 0; t < TT; t++) {
        const int rbuf = (t + 1) & 1, wbuf = t & 1;
        const char* srcB = (const char*)&g_hb[rbuf][nb][0][2 * w][0];  // +kk*4096
        const int tgt = base_d + t;

        // x for my 4 cols
        const float* xsrc = (t == 0) ? init_in : (targets + (size_t)(t - 1) * BB);
        float xv[2][2];
#pragma unroll
        for (int o = 0; o < 2; o++)
#pragma unroll
            for (int c = 0; c < 2; c++)
                xv[o][c] = __ldg(&xsrc[bb0 + w * 16 + o * 8 + 2 * tq + c]);

        // pair-local poll (wmh0 warp only): chunk j needs producers mi=4j..4j+3
        auto poll = [&](int j) {
            if (wmh == 0) {
                bool ok = true;
                int fi = 0;
                if (lane < 16)
                    fi = ((4 * j + (lane >> 2)) * 4 + nb) * 4 + (lane & 3);
                do {
                    ok = (lane < 16) ? (g_dw[fi] >= tgt) : true;
                } while (!__all_sync(0xffffffffu, ok));
                __threadfence();
            }
        };
        // pair-local cp.async of chunk j into parity p (wmh0 warp only; 8 KB)
        auto cpchunk = [&](int j, int p) {
            if (wmh == 0) {
                const uint32_t dst = sb + OFF_B + w * 16384 + p * 8192;
                const char* src = srcB + (size_t)j * 8 * 4096;   // kk stride 4096
#pragma unroll
                for (int i = 0; i < 16; i++) {
                    const int flat = i * 32 + lane;              // 0..511
                    const int kkl  = flat >> 6;
                    const int o01  = (flat >> 5) & 1;
                    const int ln   = flat & 31;
                    asm volatile("cp.async.cg.shared.global [%0], [%1], 16;"
                                 :: "r"(dst + flat * 16),
                                    "l"(src + (size_t)kkl * 4096 + o01 * 512 + ln * 16));
                }
                asm volatile("cp.async.commit_group;" ::: "memory");
            }
        };

        poll(0);
        cpchunk(0, 0);
        if (wmh == 0) asm volatile("cp.async.wait_group 0;" ::: "memory");

        float accH[2][4], accL[2][4];
#pragma unroll
        for (int o = 0; o < 2; o++)
#pragma unroll
            for (int e = 0; e < 4; e++) { accH[o][e] = 0.f; accL[o][e] = 0.f; }

#pragma unroll 1
        for (int j = 0; j < 8; j++) {
            asm volatile("bar.sync %0, 64;" :: "r"(barid) : "memory");
            if (j < 7) { poll(j + 1); cpchunk(j + 1, (j + 1) & 1); }

            const int bB = OFF_B + w * 16384 + (j & 1) * 8192 + lane * 16;
#pragma unroll
            for (int k = 0; k < 8; k++) {
                const int kk = j * 8 + k;
                const int ab = (wmh * 64 + kk) * 512 + lane * 16;
                uint4 Ah = *reinterpret_cast<const uint4*>(smem + ab);
                uint4 Al = *reinterpret_cast<const uint4*>(smem + OFF_ALO + ab);
#pragma unroll
                for (int o = 0; o < 2; o++) {
                    uint4 V = *reinterpret_cast<const uint4*>(
                        smem + bB + (k * 2 + o) * 512);
                    uint32_t Bh[2] = {V.x, V.y};
                    uint32_t Bl[2] = {V.z, V.w};
                    mma16816(accH[o], &Ah.x, Bh);
                    mma16816(accL[o], &Al.x, Bh);
                    mma16816(accL[o], &Ah.x, Bl);
                }
            }
            if (j < 7 && wmh == 0)
                asm volatile("cp.async.wait_group 0;" ::: "memory");
        }

        // ---- epilogue (pair-local): tanh, publish fused frags, y ----
        float hgv[2][2], h8v[2][2];
        float yp[2][2];
#pragma unroll
        for (int o = 0; o < 2; o++)
#pragma unroll
            for (int c = 0; c < 2; c++) {
                float pg = accH[o][c] + accL[o][c] + fmaf(xv[o][c], wih_g, bias_g);
                float p8 = accH[o][c + 2] + accL[o][c + 2] + fmaf(xv[o][c], wih_8, bias_8);
                hgv[o][c] = ftanh(pg);
                h8v[o][c] = ftanh(p8);
                yp[o][c]  = hgv[o][c] * wout_g + h8v[o][c] * wout_8;
            }

#pragma unroll
        for (int o = 0; o < 2; o++)
#pragma unroll
            for (int c = 0; c < 2; c++) {
                uint32_t P1 = (uint32_t)bhi(hgv[o][c]) | ((uint32_t)bhi(h8v[o][c]) << 16);
                uint32_t P2 = pack_bf(hgv[o][c] - bup(bhi(hgv[o][c])),
                                      h8v[o][c] - bup(bhi(h8v[o][c])));
                uint32_t q1 = __shfl_xor_sync(0xffffffffu, P1, 4);
                uint32_t q2 = __shfl_xor_sync(0xffffffffu, P2, 4);
                if ((g & 1) == 0) {
                    uint4 u;
                    u.x = __byte_perm(P1, q1, 0x5410);   // hi slot0: rows g,g+1
                    u.y = __byte_perm(P1, q1, 0x7632);   // hi slot1: rows g+8,g+9
                    u.z = __byte_perm(P2, q2, 0x5410);
                    u.w = __byte_perm(P2, q2, 0x7632);
                    g_hb[wbuf][nb][mi * 2 + wmh][2 * w + o]
                        [(2 * tq + c) * 4 + (g >> 1)] = u;
                }
            }

        // y partials: reduce over g (rows), atomicAdd per col
#pragma unroll
        for (int off = 4; off < 32; off <<= 1)
#pragma unroll
            for (int o = 0; o < 2; o++)
#pragma unroll
                for (int c = 0; c < 2; c++)
                    yp[o][c] += __shfl_xor_sync(0xffffffffu, yp[o][c], off);
        if (lane < 4) {
#pragma unroll
            for (int o = 0; o < 2; o++)
#pragma unroll
                for (int c = 0; c < 2; c++)
                    atomicAdd(&out[(size_t)t * BB + bb0 + w * 16 + o * 8 + 2 * lane + c],
                              yp[o][c]);
        }

        __threadfence();
        asm volatile("bar.sync %0, 64;" :: "r"(barid) : "memory");
        if (wmh == 0 && lane == 0) g_dw[cta * 4 + w] = base_d + t + 1;
    }
}

extern "C" void kernel_launch(void* const* d_in, const int* in_sizes, int n_in,
                              void* d_out, int out_size) {
    const float* init_in = (const float*)d_in[0];
    const float* hidden0 = (const float*)d_in[1];
    const float* targets = (const float*)d_in[2];
    const float* W_ih    = (const float*)d_in[3];
    const float* W_hh    = (const float*)d_in[4];
    const float* b_ih    = (const float*)d_in[5];
    const float* b_hh    = (const float*)d_in[6];
    const float* W_out   = (const float*)d_in[7];
    const float* b_out   = (const float*)d_in[8];
    float* out = (float*)d_out;

    cudaFuncSetAttribute(rnn_decoder_kernel,
                         cudaFuncAttributeMaxDynamicSharedMemorySize, SMEM_SZ);
    rnn_decoder_kernel<<<NCTA, NTHR, SMEM_SZ>>>(init_in, hidden0, targets, W_ih,
                                                W_hh, b_ih, b_hh, W_out, b_out,
                                                out);
}